// round 3
// baseline (speedup 1.0000x reference)
#include <cuda_runtime.h>

// Problem constants
#define BB 16
#define CC 64
#define HH 256
#define WW 256
#define HW (HH*WW)
#define KPOS 9          // 3x3
#define JDIM (CC*KPOS)  // 576

// Scratch (no allocation allowed in kernel_launch)
__device__ float g_avg[BB*CC];          // 1024
__device__ float g_wk[BB*JDIM];         // 9216 sigmoid'd dynamic weights

// ---------------------------------------------------------------------------
// Kernel 1: per-(b,c) spatial mean. At DRAM roofline (80% / 6.4 TB/s).
// ---------------------------------------------------------------------------
__global__ void avg_kernel(const float* __restrict__ x) {
    const int bc = blockIdx.x;
    const float4* p = reinterpret_cast<const float4*>(x + (size_t)bc * HW);
    const int t = threadIdx.x;     // 0..255
    float s = 0.f;
    #pragma unroll 8
    for (int i = 0; i < 64; ++i) {
        float4 v = p[i * 256 + t];
        s += (v.x + v.y) + (v.z + v.w);
    }
    __shared__ float red[256];
    red[t] = s;
    __syncthreads();
    #pragma unroll
    for (int off = 128; off > 0; off >>= 1) {
        if (t < off) red[t] += red[t + off];
        __syncthreads();
    }
    if (t == 0) g_avg[bc] = red[0] * (1.0f / (float)HW);
}

// ---------------------------------------------------------------------------
// Kernel 2: dyn = avg @ w1^T + b1 ; wk = sigmoid(dyn).
// ---------------------------------------------------------------------------
__global__ void weight_kernel(const float* __restrict__ w1,
                              const float* __restrict__ b1) {
    const int b = blockIdx.x;
    const int j = threadIdx.x;   // 0..575
    __shared__ float av[CC];
    if (j < CC) av[j] = g_avg[b * CC + j];
    __syncthreads();
    float s = b1[j];
    const float* wr = w1 + (size_t)j * CC;
    #pragma unroll 16
    for (int c = 0; c < CC; ++c) s += av[c] * wr[c];
    g_wk[b * JDIM + j] = 1.0f / (1.0f + expf(-s));
}

// ---------------------------------------------------------------------------
// Kernel 3: depthwise 3x3 conv + conv_bias, fused with (x-y)*fs*x + y.
//
// Tile: 32 rows x 256 cols per CTA, 256 threads.
// Smem layout: position p stores col (p-1); p=0 (left halo) and p=257
// (right halo) are zero. Tile stores are ALIGNED STS.128: each thread loads
// a gmem float4 (cols 4c4..4c4+3), gets the previous group's .w via
// __shfl_up, and stores {prev, x, y, z} at p=4c4 (16B aligned,
// conflict-free). Warp-boundary col (c4==32's prev) comes from one scalar
// LDG (L1/L2 hit); col 255 is patched with one STS.32 per row.
// Compute: 4 row-slices x 64 col-groups; rolling 2x6 register window,
// aligned LDS.128+LDS.64 per row, STG.128 outputs.
// ---------------------------------------------------------------------------
#define TR 32
#define SWD 260

__global__ void conv_kernel(const float* __restrict__ x,
                            const float* __restrict__ fscale,
                            const float* __restrict__ conv_bias,
                            float* __restrict__ out) {
    const int bc   = blockIdx.y;          // 0..1023
    const int c    = bc & (CC - 1);
    const int row0 = blockIdx.x * TR;
    const int t    = threadIdx.x;         // 0..255

    __shared__ float sm[(TR + 2) * SWD];
    __shared__ float wsh[KPOS];

    if (t < KPOS) wsh[t] = g_wk[bc * KPOS + t];
    if (t < TR + 2)                       // zero right halo column (p=257)
        sm[t * SWD + 257] = 0.f;

    const float* xp = x + (size_t)bc * HW;

    // Load 34 rows x 64 float4, storing shifted-by-one with aligned STS.128.
    #pragma unroll
    for (int i = t; i < (TR + 2) * 64; i += 256) {
        const int r  = i >> 6;
        const int c4 = i & 63;
        const int g  = row0 - 1 + r;
        const bool inrow = (unsigned)g < HH;
        float4 v = make_float4(0.f, 0.f, 0.f, 0.f);
        if (inrow)
            v = reinterpret_cast<const float4*>(xp + (size_t)g * WW)[c4];
        float prev = __shfl_up_sync(0xffffffffu, v.w, 1);
        if ((c4 & 31) == 0) {             // first lane of each 32-wide group
            prev = 0.f;
            if (c4 == 32 && inrow) prev = xp[(size_t)g * WW + 127];
        }
        *reinterpret_cast<float4*>(&sm[r * SWD + 4 * c4]) =
            make_float4(prev, v.x, v.y, v.z);
        if (c4 == 63) sm[r * SWD + 256] = v.w;   // col 255 -> p=256
    }
    __syncthreads();

    const float w0 = wsh[0], w1v = wsh[1], w2 = wsh[2];
    const float w3 = wsh[3], w4  = wsh[4], w5 = wsh[5];
    const float w6 = wsh[6], w7  = wsh[7], w8 = wsh[8];
    const float cb = conv_bias[c];
    const float fs = fscale[c];

    const int cg = t & 63;                 // output cols [4cg, 4cg+3]
    const int rs = t >> 6;                 // row slice 0..3 -> 8 rows each
    const int r0 = rs * 8;
    const float* s0 = &sm[r0 * SWD + 4 * cg];   // 16B aligned; p=4cg -> col 4cg-1

    float a0,a1,a2,a3,a4,a5, b0,b1,b2,b3,b4,b5;
    {
        float4 v4 = *reinterpret_cast<const float4*>(s0);
        float2 v2 = *reinterpret_cast<const float2*>(s0 + 4);
        a0=v4.x; a1=v4.y; a2=v4.z; a3=v4.w; a4=v2.x; a5=v2.y;
        v4 = *reinterpret_cast<const float4*>(s0 + SWD);
        v2 = *reinterpret_cast<const float2*>(s0 + SWD + 4);
        b0=v4.x; b1=v4.y; b2=v4.z; b3=v4.w; b4=v2.x; b5=v2.y;
    }

    float* op = out + (size_t)bc * HW + (size_t)(row0 + r0) * WW + 4 * cg;

    #pragma unroll
    for (int r = 0; r < 8; ++r) {
        const float* sc = s0 + (r + 2) * SWD;
        const float4 v4 = *reinterpret_cast<const float4*>(sc);
        const float2 v2 = *reinterpret_cast<const float2*>(sc + 4);
        const float c0=v4.x, c1=v4.y, c2=v4.z, c3=v4.w, c4f=v2.x, c5=v2.y;

        float4 o;
        {   // j = 0
            float y = cb + w0*a0 + w1v*a1 + w2*a2
                         + w3*b0 + w4 *b1 + w5*b2
                         + w6*c0 + w7 *c1 + w8*c2;
            const float xv = b1;
            o.x = (xv - y) * fs * xv + y;
        }
        {   // j = 1
            float y = cb + w0*a1 + w1v*a2 + w2*a3
                         + w3*b1 + w4 *b2 + w5*b3
                         + w6*c1 + w7 *c2 + w8*c3;
            const float xv = b2;
            o.y = (xv - y) * fs * xv + y;
        }
        {   // j = 2
            float y = cb + w0*a2 + w1v*a3 + w2*a4
                         + w3*b2 + w4 *b3 + w5*b4
                         + w6*c2 + w7 *c3 + w8*c4f;
            const float xv = b3;
            o.z = (xv - y) * fs * xv + y;
        }
        {   // j = 3
            float y = cb + w0*a3 + w1v*a4 + w2*a5
                         + w3*b3 + w4 *b4 + w5*b5
                         + w6*c3 + w7 *c4f + w8*c5;
            const float xv = b4;
            o.w = (xv - y) * fs * xv + y;
        }
        *reinterpret_cast<float4*>(op + (size_t)r * WW) = o;

        a0=b0; a1=b1; a2=b2; a3=b3; a4=b4; a5=b5;
        b0=c0; b1=c1; b2=c2; b3=c3; b4=c4f; b5=c5;
    }
}

// ---------------------------------------------------------------------------
// Launch: x, w1, b1, fscale, conv_bias (metadata order); out fp32.
// ---------------------------------------------------------------------------
extern "C" void kernel_launch(void* const* d_in, const int* in_sizes, int n_in,
                              void* d_out, int out_size) {
    const float* x         = (const float*)d_in[0];
    const float* w1        = (const float*)d_in[1];
    const float* b1        = (const float*)d_in[2];
    const float* fscale    = (const float*)d_in[3];
    const float* conv_bias = (const float*)d_in[4];
    float* out = (float*)d_out;

    avg_kernel<<<BB * CC, 256>>>(x);
    weight_kernel<<<BB, JDIM>>>(w1, b1);
    conv_kernel<<<dim3(HH / TR, BB * CC), 256>>>(x, fscale, conv_bias, out);
}

// round 4
// speedup vs baseline: 1.2885x; 1.2885x over previous
#include <cuda_runtime.h>

// Problem constants
#define BB 16
#define CC 64
#define HH 256
#define WW 256
#define HW (HH*WW)
#define KPOS 9          // 3x3
#define JDIM (CC*KPOS)  // 576

// Scratch (no allocation allowed in kernel_launch)
__device__ float g_avg[BB*CC];          // 1024
__device__ float g_wk[BB*JDIM];         // 9216 sigmoid'd dynamic weights

// ---------------------------------------------------------------------------
// Kernel 1: per-(b,c) spatial mean. At DRAM roofline (80% / 6.4 TB/s).
// ---------------------------------------------------------------------------
__global__ void avg_kernel(const float* __restrict__ x) {
    const int bc = blockIdx.x;
    const float4* p = reinterpret_cast<const float4*>(x + (size_t)bc * HW);
    const int t = threadIdx.x;     // 0..255
    float s = 0.f;
    #pragma unroll 8
    for (int i = 0; i < 64; ++i) {
        float4 v = p[i * 256 + t];
        s += (v.x + v.y) + (v.z + v.w);
    }
    __shared__ float red[256];
    red[t] = s;
    __syncthreads();
    #pragma unroll
    for (int off = 128; off > 0; off >>= 1) {
        if (t < off) red[t] += red[t + off];
        __syncthreads();
    }
    if (t == 0) g_avg[bc] = red[0] * (1.0f / (float)HW);
}

// ---------------------------------------------------------------------------
// Kernel 2: dyn = avg @ w1^T + b1 ; wk = sigmoid(dyn).
// ---------------------------------------------------------------------------
__global__ void weight_kernel(const float* __restrict__ w1,
                              const float* __restrict__ b1) {
    const int b = blockIdx.x;
    const int j = threadIdx.x;   // 0..575
    __shared__ float av[CC];
    if (j < CC) av[j] = g_avg[b * CC + j];
    __syncthreads();
    float s = b1[j];
    const float* wr = w1 + (size_t)j * CC;
    #pragma unroll 16
    for (int c = 0; c < CC; ++c) s += av[c] * wr[c];
    g_wk[b * JDIM + j] = 1.0f / (1.0f + expf(-s));
}

// ---------------------------------------------------------------------------
// Kernel 3: depthwise 3x3 conv + conv_bias, fused with (x-y)*fs*x + y.
// NO shared memory: rolling 2-row register window per thread (each input
// row is read exactly once per thread, LDG.128), horizontal neighbors via
// warp shuffles inside the compute loop. Warp-edge lanes (0 and 31) fetch
// their missing neighbor with a predicated scalar LDG (L1 hit).
// 256 threads = 4 row-slices x 64 col-groups over a 32-row x 256-col tile.
// ---------------------------------------------------------------------------
#define TR 32

// Load one image row segment (4 cols) + left/right neighbors.
__device__ __forceinline__ void load_row6(const float* __restrict__ xp,
                                          int g, int cg, int lane,
                                          float& l, float4& v, float& rt) {
    const bool inrow = (unsigned)g < HH;
    v = make_float4(0.f, 0.f, 0.f, 0.f);
    if (inrow)
        v = reinterpret_cast<const float4*>(xp + (size_t)g * WW)[cg];
    l  = __shfl_up_sync(0xffffffffu, v.w, 1);
    rt = __shfl_down_sync(0xffffffffu, v.x, 1);
    if (lane == 0) {                    // cg is 0 or 32
        l = 0.f;
        if ((cg & 32) && inrow) l = __ldg(xp + (size_t)g * WW + 127);
    }
    if (lane == 31) {                   // cg is 31 or 63
        rt = 0.f;
        if (!(cg & 32) && inrow) rt = __ldg(xp + (size_t)g * WW + 128);
    }
}

__global__ void conv_kernel(const float* __restrict__ x,
                            const float* __restrict__ fscale,
                            const float* __restrict__ conv_bias,
                            float* __restrict__ out) {
    const int bc   = blockIdx.y;          // 0..1023
    const int c    = bc & (CC - 1);
    const int row0 = blockIdx.x * TR;
    const int t    = threadIdx.x;         // 0..255
    const int lane = t & 31;
    const int cg   = t & 63;              // output cols [4cg, 4cg+3]
    const int rs   = t >> 6;              // row slice 0..3 (8 rows each)
    const int g0   = row0 + rs * 8;       // first output row

    const float* wp = g_wk + bc * KPOS;   // uniform within block -> broadcast
    const float w0 = __ldg(wp + 0), w1v = __ldg(wp + 1), w2 = __ldg(wp + 2);
    const float w3 = __ldg(wp + 3), w4  = __ldg(wp + 4), w5 = __ldg(wp + 5);
    const float w6 = __ldg(wp + 6), w7  = __ldg(wp + 7), w8 = __ldg(wp + 8);
    const float cb = __ldg(conv_bias + c);
    const float fs = __ldg(fscale + c);

    const float* xp = x + (size_t)bc * HW;

    // Rolling window: row a = g-1 (top), row b = g (center)
    float  al, ar, bl, br;
    float4 av, bv;
    load_row6(xp, g0 - 1, cg, lane, al, av, ar);
    load_row6(xp, g0,     cg, lane, bl, bv, br);

    float* op = out + (size_t)bc * HW + (size_t)g0 * WW + 4 * cg;

    #pragma unroll
    for (int r = 0; r < 8; ++r) {
        float  cl, cr;
        float4 cv;
        load_row6(xp, g0 + r + 1, cg, lane, cl, cv, cr);

        float4 o;
        {   // col 4cg
            float y = cb + w0*al   + w1v*av.x + w2*av.y
                         + w3*bl   + w4 *bv.x + w5*bv.y
                         + w6*cl   + w7 *cv.x + w8*cv.y;
            const float xv = bv.x;
            o.x = (xv - y) * fs * xv + y;
        }
        {   // col 4cg+1
            float y = cb + w0*av.x + w1v*av.y + w2*av.z
                         + w3*bv.x + w4 *bv.y + w5*bv.z
                         + w6*cv.x + w7 *cv.y + w8*cv.z;
            const float xv = bv.y;
            o.y = (xv - y) * fs * xv + y;
        }
        {   // col 4cg+2
            float y = cb + w0*av.y + w1v*av.z + w2*av.w
                         + w3*bv.y + w4 *bv.z + w5*bv.w
                         + w6*cv.y + w7 *cv.z + w8*cv.w;
            const float xv = bv.z;
            o.z = (xv - y) * fs * xv + y;
        }
        {   // col 4cg+3
            float y = cb + w0*av.z + w1v*av.w + w2*ar
                         + w3*bv.z + w4 *bv.w + w5*br
                         + w6*cv.z + w7 *cv.w + w8*cr;
            const float xv = bv.w;
            o.w = (xv - y) * fs * xv + y;
        }
        *reinterpret_cast<float4*>(op + (size_t)r * WW) = o;

        al = bl; av = bv; ar = br;
        bl = cl; bv = cv; br = cr;
    }
}

// ---------------------------------------------------------------------------
// Launch: x, w1, b1, fscale, conv_bias (metadata order); out fp32.
// ---------------------------------------------------------------------------
extern "C" void kernel_launch(void* const* d_in, const int* in_sizes, int n_in,
                              void* d_out, int out_size) {
    const float* x         = (const float*)d_in[0];
    const float* w1        = (const float*)d_in[1];
    const float* b1        = (const float*)d_in[2];
    const float* fscale    = (const float*)d_in[3];
    const float* conv_bias = (const float*)d_in[4];
    float* out = (float*)d_out;

    avg_kernel<<<BB * CC, 256>>>(x);
    weight_kernel<<<BB, JDIM>>>(w1, b1);
    conv_kernel<<<dim3(HH / TR, BB * CC), 256>>>(x, fscale, conv_bias, out);
}

// round 5
// speedup vs baseline: 1.3144x; 1.0201x over previous
#include <cuda_runtime.h>

// Problem constants
#define BB 16
#define CC 64
#define HH 256
#define WW 256
#define HW (HH*WW)
#define KPOS 9          // 3x3
#define JDIM (CC*KPOS)  // 576

// Scratch (no allocation allowed in kernel_launch)
__device__ float g_avg[BB*CC];          // 1024
__device__ float g_wk[BB*JDIM];         // 9216 sigmoid'd dynamic weights

// ---------------------------------------------------------------------------
// Kernel 1: per-(b,c) spatial mean. At DRAM roofline (80% / 6.4 TB/s).
// ---------------------------------------------------------------------------
__global__ void avg_kernel(const float* __restrict__ x) {
    const int bc = blockIdx.x;
    const float4* p = reinterpret_cast<const float4*>(x + (size_t)bc * HW);
    const int t = threadIdx.x;     // 0..255
    float s = 0.f;
    #pragma unroll 8
    for (int i = 0; i < 64; ++i) {
        float4 v = p[i * 256 + t];
        s += (v.x + v.y) + (v.z + v.w);
    }
    __shared__ float red[256];
    red[t] = s;
    __syncthreads();
    #pragma unroll
    for (int off = 128; off > 0; off >>= 1) {
        if (t < off) red[t] += red[t + off];
        __syncthreads();
    }
    if (t == 0) g_avg[bc] = red[0] * (1.0f / (float)HW);
}

// ---------------------------------------------------------------------------
// Kernel 2: dyn = avg @ w1^T + b1 ; wk = sigmoid(dyn).
// ---------------------------------------------------------------------------
__global__ void weight_kernel(const float* __restrict__ w1,
                              const float* __restrict__ b1) {
    const int b = blockIdx.x;
    const int j = threadIdx.x;   // 0..575
    __shared__ float av[CC];
    if (j < CC) av[j] = g_avg[b * CC + j];
    __syncthreads();
    float s = b1[j];
    const float* wr = w1 + (size_t)j * CC;
    #pragma unroll 16
    for (int c = 0; c < CC; ++c) s += av[c] * wr[c];
    g_wk[b * JDIM + j] = 1.0f / (1.0f + expf(-s));
}

// ---------------------------------------------------------------------------
// Kernel 3: depthwise 3x3 conv + conv_bias, fused with (x-y)*fs*x + y.
// 8-col-per-thread register stencil. No smem, no shuffles.
// Thread (u, rs): cols [8u, 8u+7], rows [8rs, 8rs+7] of a 64x256 CTA tile.
// Per row: 2 aligned LDG.128 + 2 scalar halo LDG (L1 hits). Rolling 3-row
// x 10-col register window. Streaming STG.128 x2 for outputs.
// ---------------------------------------------------------------------------
#define TRC 64   // rows per CTA

__device__ __forceinline__ void load_row10(const float* __restrict__ xp,
                                           int g, int u, int co,
                                           float* __restrict__ w) {
    float4 v0 = make_float4(0.f,0.f,0.f,0.f);
    float4 v1 = v0;
    float l = 0.f, r = 0.f;
    if ((unsigned)g < HH) {
        const float* rowp = xp + (size_t)g * WW;
        v0 = *reinterpret_cast<const float4*>(rowp + co);
        v1 = *reinterpret_cast<const float4*>(rowp + co + 4);
        if (u > 0)  l = __ldg(rowp + co - 1);
        if (u < 31) r = __ldg(rowp + co + 8);
    }
    w[0]=l;    w[1]=v0.x; w[2]=v0.y; w[3]=v0.z; w[4]=v0.w;
    w[5]=v1.x; w[6]=v1.y; w[7]=v1.z; w[8]=v1.w; w[9]=r;
}

__global__ void __launch_bounds__(256) conv_kernel(
        const float* __restrict__ x,
        const float* __restrict__ fscale,
        const float* __restrict__ conv_bias,
        float* __restrict__ out) {
    const int bc   = blockIdx.y;          // 0..1023
    const int c    = bc & (CC - 1);
    const int row0 = blockIdx.x * TRC;
    const int t    = threadIdx.x;         // 0..255
    const int u    = t & 31;              // col group: cols [8u, 8u+7]
    const int rs   = t >> 5;              // row slice 0..7 (8 rows each)
    const int g0   = row0 + rs * 8;
    const int co   = u * 8;

    const float* wp = g_wk + bc * KPOS;   // uniform within block
    const float w0 = __ldg(wp + 0), w1v = __ldg(wp + 1), w2 = __ldg(wp + 2);
    const float w3 = __ldg(wp + 3), w4  = __ldg(wp + 4), w5 = __ldg(wp + 5);
    const float w6 = __ldg(wp + 6), w7  = __ldg(wp + 7), w8 = __ldg(wp + 8);
    const float cb = __ldg(conv_bias + c);
    const float fs = __ldg(fscale + c);

    const float* xp = x + (size_t)bc * HW;

    float A[10], B[10], C[10];
    load_row10(xp, g0 - 1, u, co, A);
    load_row10(xp, g0,     u, co, B);

    float* op = out + (size_t)bc * HW + (size_t)g0 * WW + co;

    #pragma unroll
    for (int r = 0; r < 8; ++r) {
        load_row10(xp, g0 + r + 1, u, co, C);

        float o[8];
        #pragma unroll
        for (int j = 0; j < 8; ++j) {
            float y = cb + w0*A[j] + w1v*A[j+1] + w2*A[j+2]
                         + w3*B[j] + w4 *B[j+1] + w5*B[j+2]
                         + w6*C[j] + w7 *C[j+1] + w8*C[j+2];
            const float xv = B[j+1];
            o[j] = (xv - y) * fs * xv + y;
        }
        __stcs(reinterpret_cast<float4*>(op + (size_t)r * WW),
               make_float4(o[0], o[1], o[2], o[3]));
        __stcs(reinterpret_cast<float4*>(op + (size_t)r * WW + 4),
               make_float4(o[4], o[5], o[6], o[7]));

        #pragma unroll
        for (int j = 0; j < 10; ++j) { A[j] = B[j]; B[j] = C[j]; }
    }
}

// ---------------------------------------------------------------------------
// Launch: x, w1, b1, fscale, conv_bias (metadata order); out fp32.
// ---------------------------------------------------------------------------
extern "C" void kernel_launch(void* const* d_in, const int* in_sizes, int n_in,
                              void* d_out, int out_size) {
    const float* x         = (const float*)d_in[0];
    const float* w1        = (const float*)d_in[1];
    const float* b1        = (const float*)d_in[2];
    const float* fscale    = (const float*)d_in[3];
    const float* conv_bias = (const float*)d_in[4];
    float* out = (float*)d_out;

    avg_kernel<<<BB * CC, 256>>>(x);
    weight_kernel<<<BB, JDIM>>>(w1, b1);
    conv_kernel<<<dim3(HH / TRC, BB * CC), 256>>>(x, fscale, conv_bias, out);
}